// round 14
// baseline (speedup 1.0000x reference)
#include <cuda_runtime.h>
#include <cuda_fp16.h>
#include <cstdint>

#define NN   100000
#define DEG  8
#define HH   128
#define KTOT 1024          // DEG*HH
#define NOUT 384           // 3*HH

// ---------------- device weight images (single fp16) ----------------
__device__ __align__(16) __half g_w1[DEG * HH * HH];      // Uf^T  [d][n][k]
__device__ __align__(16) __half g_w2[NOUT * KTOT];        // Ua^T  [n'][k] interleaved

// ---------------- helpers ----------------
static __device__ __forceinline__ uint32_t smem_u32(const void* p) {
    uint32_t a;
    asm("{ .reg .u64 t; cvta.to.shared.u64 t, %1; cvt.u32.u64 %0, t; }" : "=r"(a) : "l"(p));
    return a;
}
static __device__ __forceinline__ void ldmx4(uint32_t r[4], uint32_t addr) {
    asm volatile("ldmatrix.sync.aligned.m8n8.x4.shared.b16 {%0,%1,%2,%3}, [%4];"
                 : "=r"(r[0]), "=r"(r[1]), "=r"(r[2]), "=r"(r[3]) : "r"(addr));
}
static __device__ __forceinline__ void mma16816(float c[4], const uint32_t a[4], const uint32_t b[2]) {
    asm volatile("mma.sync.aligned.m16n8k16.row.col.f32.f16.f16.f32 "
                 "{%0,%1,%2,%3},{%4,%5,%6,%7},{%8,%9},{%0,%1,%2,%3};"
                 : "+f"(c[0]), "+f"(c[1]), "+f"(c[2]), "+f"(c[3])
                 : "r"(a[0]), "r"(a[1]), "r"(a[2]), "r"(a[3]), "r"(b[0]), "r"(b[1]));
}
static __device__ __forceinline__ void cp16(uint32_t dst, const void* src) {
    asm volatile("cp.async.cg.shared.global [%0], [%1], 16;"
                 :: "r"(dst), "l"(__cvta_generic_to_global(src)) : "memory");
}
#define CP_COMMIT() asm volatile("cp.async.commit_group;" ::: "memory")
#define CP_WAIT0()  asm volatile("cp.async.wait_group 0;" ::: "memory")

static __device__ __forceinline__ float sigm(float x) { return 1.f / (1.f + __expf(-x)); }
static __device__ __forceinline__ uint32_t pack2h(float a, float b) {
    __half2 h = __floats2half2_rn(a, b);
    return *reinterpret_cast<uint32_t*>(&h);
}

// ---------------- prep: transpose weights to fp16 ----------------
__global__ void prep_weights(const float* __restrict__ Uf, const float* __restrict__ Ua) {
    int t = blockIdx.x * blockDim.x + threadIdx.x;
    if (t < DEG * HH * HH) {                 // W1: [d][n][k] = Uf[d][k][n]
        int k = t & 127, n = (t >> 7) & 127, d = t >> 14;
        g_w1[t] = __float2half_rn(Uf[((size_t)d * HH + k) * HH + n]);
        return;
    }
    int u = t - DEG * HH * HH;
    if (u < NOUT * KTOT) {                   // W2: n' = grp*24 + ch*8 + c8
        int k = u & 1023, np = u >> 10;
        int grp = np / 24, rem = np - grp * 24;
        int ch = rem >> 3, c8 = rem & 7;
        int col = grp * 8 + c8;
        int d = k >> 7, h = k & 127;
        g_w2[u] = __float2half_rn(Ua[((size_t)d * HH + h) * NOUT + ch * HH + col]);
    }
}

// =====================================================================
// Fused kernel: 256 thr (8 warps: 4m x 2n), M=64, quarter-N split.
// blockIdx.y = q: iou rows [q*96, q*96+96) (interleaved; output cols
// [q*32, q*32+32)) + f cols [q*32, q*32+32).
// K-chunk = 64 (16 iterations); f epilogue every 2 chunks (per d).
// =====================================================================
#define BST   144          // 128B data + 16B pad
#define S_BI  0            // B iou : 96*144 = 13824
#define S_BF  13824        // B f   : 32*144 =  4608
#define S_SA  18432        // A     : 64*144 =  9216
#define STAGE 27648
#define SMEM_TOTAL (2 * STAGE)   // 55296

__global__ __launch_bounds__(256, 3)
void fused_cell(const float* __restrict__ nh, const float* __restrict__ ncv,
                const float* __restrict__ f_in, const float* __restrict__ iou_in,
                const float* __restrict__ bf, const float* __restrict__ ba,
                float* __restrict__ out) {
    extern __shared__ unsigned char smb[];
    const uint32_t sb = smem_u32(smb);
    const int tid = threadIdx.x, wid = tid >> 5, l = tid & 31;
    const int wm = wid >> 1, wn = wid & 1;      // 4 m-warps x 2 n-warps
    const int nb = blockIdx.x * 64;
    const int q = blockIdx.y;                   // 0..3
    const int brow0 = q * 96;                   // iou B rows
    const int fcol0 = q * 32;                   // f (W1) column base

    const uint32_t aoff = (uint32_t)(wm * 16 + (l & 15)) * BST + (uint32_t)(l >> 4) * 16;
    uint32_t boff[3];
#pragma unroll
    for (int p = 0; p < 3; p++)
        boff[p] = (uint32_t)(wn * 48 + p * 16 + (l & 7) + ((l >> 4) ? 8 : 0)) * BST
                + (uint32_t)((l >> 3) & 1) * 16;
    const uint32_t bfoff = (uint32_t)(wn * 16 + (l & 7) + ((l >> 4) ? 8 : 0)) * BST
                         + (uint32_t)((l >> 3) & 1) * 16;

    float acc[6][4];                   // iou (idx = g*3+gate blocks of 8 rows)
    float accf[2][4], cag[2][4];       // f + c_aggr (16 cols per warp)
#pragma unroll
    for (int b = 0; b < 6; b++)
#pragma unroll
        for (int c = 0; c < 4; c++) acc[b][c] = 0.f;
#pragma unroll
    for (int b = 0; b < 2; b++)
#pragma unroll
        for (int c = 0; c < 4; c++) { accf[b][c] = 0.f; cag[b][c] = 0.f; }

    const int arow = tid >> 2, aq = tid & 3;    // 64 rows x 4 sixteens
    const int anode = nb + arow;
    const float* asrc = nh + (size_t)anode * KTOT + aq * 16;

    // ---- prologue: chunk 0 ----
    {
#pragma unroll
        for (int i = 0; i < 3; i++) {           // B iou: 768 granules (96 rows x 8)
            int idx = tid + i * 256;
            int r = idx >> 3, g = idx & 7;
            cp16(sb + S_BI + r * BST + g * 16,
                 (const char*)(g_w2 + (size_t)(brow0 + r) * KTOT) + g * 16);
        }
        {                                        // B f: 256 granules (32 rows x 8)
            int r = tid >> 3, g = tid & 7;
            cp16(sb + S_BF + r * BST + g * 16,
                 (const char*)(g_w1 + (size_t)(fcol0 + r) * HH) + g * 16);
        }
        CP_COMMIT();
        float4 v0 = make_float4(0,0,0,0), v1 = v0, v2 = v0, v3 = v0;
        if (anode < NN) {
            v0 = *(const float4*)(asrc);
            v1 = *(const float4*)(asrc + 4);
            v2 = *(const float4*)(asrc + 8);
            v3 = *(const float4*)(asrc + 12);
        }
        uint32_t h0 = pack2h(v0.x, v0.y), h1 = pack2h(v0.z, v0.w);
        uint32_t h2 = pack2h(v1.x, v1.y), h3 = pack2h(v1.z, v1.w);
        uint32_t h4 = pack2h(v2.x, v2.y), h5 = pack2h(v2.z, v2.w);
        uint32_t h6 = pack2h(v3.x, v3.y), h7 = pack2h(v3.z, v3.w);
        uint32_t ad = sb + S_SA + arow * BST + aq * 32;
        asm volatile("st.shared.v4.b32 [%0], {%1,%2,%3,%4};" :: "r"(ad), "r"(h0), "r"(h1), "r"(h2), "r"(h3) : "memory");
        asm volatile("st.shared.v4.b32 [%0], {%1,%2,%3,%4};" :: "r"(ad + 16), "r"(h4), "r"(h5), "r"(h6), "r"(h7) : "memory");
        CP_WAIT0();
        __syncthreads();
    }

    for (int kc = 0; kc < 16; kc++) {
        const uint32_t cur = sb + (kc & 1) * STAGE;
        const uint32_t nxt = sb + ((kc + 1) & 1) * STAGE;
        const bool have_next = (kc < 15);

        float4 v0, v1, v2, v3;
        if (have_next) {
            v0 = make_float4(0,0,0,0); v1 = v0; v2 = v0; v3 = v0;
            if (anode < NN) {
                const float* s = asrc + (kc + 1) * 64;
                v0 = *(const float4*)(s);
                v1 = *(const float4*)(s + 4);
                v2 = *(const float4*)(s + 8);
                v3 = *(const float4*)(s + 12);
            }
            int dn = (kc + 1) >> 1, hf = (kc + 1) & 1;
#pragma unroll
            for (int i = 0; i < 3; i++) {
                int idx = tid + i * 256;
                int r = idx >> 3, g = idx & 7;
                cp16(nxt + S_BI + r * BST + g * 16,
                     (const char*)(g_w2 + (size_t)(brow0 + r) * KTOT) + (kc + 1) * 128 + g * 16);
            }
            {
                int r = tid >> 3, g = tid & 7;
                cp16(nxt + S_BF + r * BST + g * 16,
                     (const char*)(g_w1 + ((size_t)dn * HH + fcol0 + r) * HH) + hf * 128 + g * 16);
            }
            CP_COMMIT();
        }

        // ---- compute: 4 k-steps of 16 ----
#pragma unroll
        for (int ks = 0; ks < 4; ks++) {
            uint32_t ah[4];
            ldmx4(ah, cur + S_SA + aoff + ks * 32);
#pragma unroll
            for (int p = 0; p < 3; p++) {
                uint32_t rb[4];
                ldmx4(rb, cur + S_BI + boff[p] + ks * 32);
                mma16816(acc[p*2+0], ah, rb + 0);
                mma16816(acc[p*2+1], ah, rb + 2);
            }
            {
                uint32_t rb[4];
                ldmx4(rb, cur + S_BF + bfoff + ks * 32);
                mma16816(accf[0], ah, rb + 0);
                mma16816(accf[1], ah, rb + 2);
            }
        }

        // ---- f epilogue at end of each d (every 2 chunks) ----
        if (kc & 1) {
            const int d = kc >> 1;
#pragma unroll
            for (int rh = 0; rh < 2; rh++) {
                int node = nb + wm * 16 + (l >> 2) + rh * 8;
                if (node < NN) {
#pragma unroll
                    for (int fn = 0; fn < 2; fn++) {
                        int col = fcol0 + wn * 16 + fn * 8 + (l & 3) * 2;
                        float2 fi  = *(const float2*)(f_in + (size_t)node * HH + col);
                        float2 nc2 = *(const float2*)(ncv + ((size_t)node * DEG + d) * HH + col);
                        float2 bf2 = *(const float2*)(bf + d * HH + col);
                        cag[fn][rh*2+0] += sigm(accf[fn][rh*2+0] + bf2.x + fi.x) * nc2.x;
                        cag[fn][rh*2+1] += sigm(accf[fn][rh*2+1] + bf2.y + fi.y) * nc2.y;
                    }
                }
#pragma unroll
                for (int fn = 0; fn < 2; fn++) {
                    accf[fn][rh*2+0] = 0.f;
                    accf[fn][rh*2+1] = 0.f;
                }
            }
        }

        if (have_next) {
            uint32_t h0 = pack2h(v0.x, v0.y), h1 = pack2h(v0.z, v0.w);
            uint32_t h2 = pack2h(v1.x, v1.y), h3 = pack2h(v1.z, v1.w);
            uint32_t h4 = pack2h(v2.x, v2.y), h5 = pack2h(v2.z, v2.w);
            uint32_t h6 = pack2h(v3.x, v3.y), h7 = pack2h(v3.z, v3.w);
            uint32_t ad = nxt + S_SA + arow * BST + aq * 32;
            asm volatile("st.shared.v4.b32 [%0], {%1,%2,%3,%4};" :: "r"(ad), "r"(h0), "r"(h1), "r"(h2), "r"(h3) : "memory");
            asm volatile("st.shared.v4.b32 [%0], {%1,%2,%3,%4};" :: "r"(ad + 16), "r"(h4), "r"(h5), "r"(h6), "r"(h7) : "memory");
            CP_WAIT0();
            __syncthreads();
        }
    }

    // ---- final epilogue: output cols [q*32, q*32+32), cag in regs ----
#pragma unroll
    for (int rh = 0; rh < 2; rh++) {
        int node = nb + wm * 16 + (l >> 2) + rh * 8;
        if (node >= NN) continue;
        const float* ib = iou_in + (size_t)node * NOUT;
#pragma unroll
        for (int g = 0; g < 2; g++) {
            int col = (q * 4 + wn * 2 + g) * 8 + (l & 3) * 2;   // == fcol0 + wn*16 + g*8 + (l&3)*2
            float2 ii = *(const float2*)(ib + col);
            float2 oo = *(const float2*)(ib + HH + col);
            float2 uu = *(const float2*)(ib + 2 * HH + col);
            float2 bi = *(const float2*)(ba + col);
            float2 bo = *(const float2*)(ba + HH + col);
            float2 bu = *(const float2*)(ba + 2 * HH + col);
            float hv[2], cv[2];
#pragma unroll
            for (int e = 0; e < 2; e++) {
                float iv = acc[g*3+0][rh*2+e] + ((e) ? ii.y + bi.y : ii.x + bi.x);
                float ov = acc[g*3+1][rh*2+e] + ((e) ? oo.y + bo.y : oo.x + bo.x);
                float uv = acc[g*3+2][rh*2+e] + ((e) ? uu.y + bu.y : uu.x + bu.x);
                float c  = sigm(iv) * tanhf(uv) + cag[g][rh*2+e];
                cv[e] = c;
                hv[e] = sigm(ov) * tanhf(c);
            }
            *(float2*)(out + (size_t)node * HH + col) = make_float2(hv[0], hv[1]);
            *(float2*)(out + (size_t)NN * HH + (size_t)node * HH + col) = make_float2(cv[0], cv[1]);
        }
    }
}

// ---------------- launch ----------------
extern "C" void kernel_launch(void* const* d_in, const int* in_sizes, int n_in,
                              void* d_out, int out_size) {
    const float* nh     = (const float*)d_in[0];
    const float* ncv    = (const float*)d_in[1];
    const float* f_in   = (const float*)d_in[2];
    const float* iou_in = (const float*)d_in[3];
    const float* Uf     = (const float*)d_in[4];
    const float* bf     = (const float*)d_in[5];
    const float* Ua     = (const float*)d_in[6];
    const float* ba     = (const float*)d_in[7];
    float* out = (float*)d_out;

    prep_weights<<<2048, 256>>>(Uf, Ua);

    cudaFuncSetAttribute(fused_cell, cudaFuncAttributeMaxDynamicSharedMemorySize, SMEM_TOTAL);
    dim3 grid((NN + 63) / 64, 4);
    fused_cell<<<grid, 256, SMEM_TOTAL>>>(nh, ncv, f_in, iou_in, bf, ba, out);
}

// round 16
// speedup vs baseline: 1.0759x; 1.0759x over previous
#include <cuda_runtime.h>
#include <cuda_fp16.h>
#include <cstdint>

#define NN    100000
#define NPAD  100032           // NN rounded up to 64 (grid coverage), zero-padded
#define DEG   8
#define HH    128
#define KTOT  1024             // DEG*HH
#define NOUT  384              // 3*HH

// ---------------- device images ----------------
__device__ __align__(16) __half g_ah[(size_t)NPAD * KTOT];   // nh in fp16 (zero-padded rows)
__device__ __align__(16) __half g_w1[DEG * HH * HH];         // Uf^T  [d][n][k]
__device__ __align__(16) __half g_w2[NOUT * KTOT];           // Ua^T  [n'][k] interleaved

// ---------------- helpers ----------------
static __device__ __forceinline__ uint32_t smem_u32(const void* p) {
    uint32_t a;
    asm("{ .reg .u64 t; cvta.to.shared.u64 t, %1; cvt.u32.u64 %0, t; }" : "=r"(a) : "l"(p));
    return a;
}
static __device__ __forceinline__ void ldmx4(uint32_t r[4], uint32_t addr) {
    asm volatile("ldmatrix.sync.aligned.m8n8.x4.shared.b16 {%0,%1,%2,%3}, [%4];"
                 : "=r"(r[0]), "=r"(r[1]), "=r"(r[2]), "=r"(r[3]) : "r"(addr));
}
static __device__ __forceinline__ void mma16816(float c[4], const uint32_t a[4], const uint32_t b[2]) {
    asm volatile("mma.sync.aligned.m16n8k16.row.col.f32.f16.f16.f32 "
                 "{%0,%1,%2,%3},{%4,%5,%6,%7},{%8,%9},{%0,%1,%2,%3};"
                 : "+f"(c[0]), "+f"(c[1]), "+f"(c[2]), "+f"(c[3])
                 : "r"(a[0]), "r"(a[1]), "r"(a[2]), "r"(a[3]), "r"(b[0]), "r"(b[1]));
}
static __device__ __forceinline__ void cp16(uint32_t dst, const void* src) {
    asm volatile("cp.async.cg.shared.global [%0], [%1], 16;"
                 :: "r"(dst), "l"(__cvta_generic_to_global(src)) : "memory");
}
#define CP_COMMIT() asm volatile("cp.async.commit_group;" ::: "memory")
#define CP_WAIT0()  asm volatile("cp.async.wait_group 0;" ::: "memory")

static __device__ __forceinline__ float sigm(float x) { return 1.f / (1.f + __expf(-x)); }

// ---------------- prep 1: weights -> fp16 (transposed) ----------------
__global__ void prep_weights(const float* __restrict__ Uf, const float* __restrict__ Ua) {
    int t = blockIdx.x * blockDim.x + threadIdx.x;
    if (t < DEG * HH * HH) {                 // W1: [d][n][k] = Uf[d][k][n]
        int k = t & 127, n = (t >> 7) & 127, d = t >> 14;
        g_w1[t] = __float2half_rn(Uf[((size_t)d * HH + k) * HH + n]);
        return;
    }
    int u = t - DEG * HH * HH;
    if (u < NOUT * KTOT) {                   // W2: n' = grp*24 + ch*8 + c8
        int k = u & 1023, np = u >> 10;
        int grp = np / 24, rem = np - grp * 24;
        int ch = rem >> 3, c8 = rem & 7;
        int col = grp * 8 + c8;
        int d = k >> 7, h = k & 127;
        g_w2[u] = __float2half_rn(Ua[((size_t)d * HH + h) * NOUT + ch * HH + col]);
    }
}

// ---------------- prep 2: nh -> fp16 (zero-pad tail rows) ----------------
// one thread = 8 halfs (16B store). total NPAD*KTOT/8 threads.
__global__ void prep_a(const float* __restrict__ nh) {
    size_t idx = (size_t)blockIdx.x * blockDim.x + threadIdx.x;   // 0 .. NPAD*128-1
    if (idx >= (size_t)NPAD * (KTOT / 8)) return;
    int row = (int)(idx >> 7);
    int g8  = (int)(idx & 127);
    uint4 outv;
    if (row < NN) {
        const float* s = nh + (size_t)row * KTOT + g8 * 8;
        float4 a = *(const float4*)(s);
        float4 b = *(const float4*)(s + 4);
        __half2 p0 = __floats2half2_rn(a.x, a.y);
        __half2 p1 = __floats2half2_rn(a.z, a.w);
        __half2 p2 = __floats2half2_rn(b.x, b.y);
        __half2 p3 = __floats2half2_rn(b.z, b.w);
        outv.x = *reinterpret_cast<uint32_t*>(&p0);
        outv.y = *reinterpret_cast<uint32_t*>(&p1);
        outv.z = *reinterpret_cast<uint32_t*>(&p2);
        outv.w = *reinterpret_cast<uint32_t*>(&p3);
    } else {
        outv = make_uint4(0, 0, 0, 0);
    }
    *(uint4*)(g_ah + (size_t)row * KTOT + g8 * 8) = outv;
}

// =====================================================================
// Fused kernel: 256 thr (8 warps 2m x 4n), M=64, N-half split (R13 layout).
// K-chunk = 64 (16 iterations).  ALL smem fills via cp.async (A is fp16).
// Per half-CTA: iou N=192 (interleaved half) + f N=64.
// =====================================================================
#define BST   144          // 128B data + 16B pad
#define S_BI  0            // B iou : 192*144 = 27648
#define S_BF  27648        // B f   :  64*144 =  9216
#define S_SA  36864        // A     :  64*144 =  9216
#define STAGE 46080
#define SMEM_TOTAL (2 * STAGE)   // 92160

__global__ __launch_bounds__(256, 2)
void fused_cell(const float* __restrict__ ncv,
                const float* __restrict__ f_in, const float* __restrict__ iou_in,
                const float* __restrict__ bf, const float* __restrict__ ba,
                float* __restrict__ out) {
    extern __shared__ unsigned char smb[];
    const uint32_t sb = smem_u32(smb);
    const int tid = threadIdx.x, wid = tid >> 5, l = tid & 31;
    const int wm = wid & 1, wn = wid >> 1;      // 2 m-warps x 4 n-warps
    const int nb = blockIdx.x * 64;
    const int nhalf = blockIdx.y;               // 0 or 1
    const int brow0 = nhalf * 192;              // iou B rows
    const int fcol0 = nhalf * 64;               // f (W1) column base

    uint32_t aoff[2], boff[3], bfoff;
#pragma unroll
    for (int fm = 0; fm < 2; fm++)
        aoff[fm] = (uint32_t)(wm * 32 + fm * 16 + (l & 15)) * BST + (uint32_t)(l >> 4) * 16;
#pragma unroll
    for (int p = 0; p < 3; p++)
        boff[p] = (uint32_t)(wn * 48 + p * 16 + (l & 7) + ((l >> 4) ? 8 : 0)) * BST
                + (uint32_t)((l >> 3) & 1) * 16;
    bfoff = (uint32_t)(wn * 16 + (l & 7) + ((l >> 4) ? 8 : 0)) * BST
          + (uint32_t)((l >> 3) & 1) * 16;

    float acc[2][6][4];                  // iou
    float accf[2][2][4], cag[2][2][4];   // f + c_aggr (16 cols per warp)
#pragma unroll
    for (int a = 0; a < 2; a++) {
#pragma unroll
        for (int b = 0; b < 6; b++)
#pragma unroll
            for (int c = 0; c < 4; c++) acc[a][b][c] = 0.f;
#pragma unroll
        for (int b = 0; b < 2; b++)
#pragma unroll
            for (int c = 0; c < 4; c++) { accf[a][b][c] = 0.f; cag[a][b][c] = 0.f; }
    }

    // cp.async role assignments (granule = 16B):
    //   B iou : 192 rows x 8 = 1536 granules -> 6 per thread
    //   B f   :  64 rows x 8 =  512 granules -> 2 per thread
    //   A     :  64 rows x 8 =  512 granules -> 2 per thread
#define LOAD_CHUNK(dstbase, KC)                                                                 \
    do {                                                                                        \
        _Pragma("unroll")                                                                       \
        for (int i = 0; i < 6; i++) {                                                           \
            int idx = tid + i * 256;                                                            \
            int r = idx >> 3, g = idx & 7;                                                      \
            cp16((dstbase) + S_BI + r * BST + g * 16,                                           \
                 (const char*)(g_w2 + (size_t)(brow0 + r) * KTOT) + (KC) * 128 + g * 16);       \
        }                                                                                       \
        _Pragma("unroll")                                                                       \
        for (int i = 0; i < 2; i++) {                                                           \
            int idx = tid + i * 256;                                                            \
            int r = idx >> 3, g = idx & 7;                                                      \
            int dd = (KC) >> 1, hf = (KC) & 1;                                                  \
            cp16((dstbase) + S_BF + r * BST + g * 16,                                           \
                 (const char*)(g_w1 + ((size_t)dd * HH + fcol0 + r) * HH) + hf * 128 + g * 16); \
            cp16((dstbase) + S_SA + r * BST + g * 16,                                           \
                 (const char*)(g_ah + (size_t)(nb + r) * KTOT) + (KC) * 128 + g * 16);          \
        }                                                                                       \
    } while (0)

    // ---- prologue: chunk 0 ----
    LOAD_CHUNK(sb, 0);
    CP_COMMIT();
    CP_WAIT0();
    __syncthreads();

    for (int kc = 0; kc < 16; kc++) {
        const uint32_t cur = sb + (kc & 1) * STAGE;
        const uint32_t nxt = sb + ((kc + 1) & 1) * STAGE;
        const bool have_next = (kc < 15);

        if (have_next) {
            LOAD_CHUNK(nxt, kc + 1);
            CP_COMMIT();
        }

        // ---- compute: 4 k-steps of 16 ----
#pragma unroll
        for (int ks = 0; ks < 4; ks++) {
            uint32_t ah[2][4];
#pragma unroll
            for (int fm = 0; fm < 2; fm++)
                ldmx4(ah[fm], cur + S_SA + aoff[fm] + ks * 32);
#pragma unroll
            for (int p = 0; p < 3; p++) {
                uint32_t rb[4];
                ldmx4(rb, cur + S_BI + boff[p] + ks * 32);
                mma16816(acc[0][p*2+0], ah[0], rb + 0);
                mma16816(acc[0][p*2+1], ah[0], rb + 2);
                mma16816(acc[1][p*2+0], ah[1], rb + 0);
                mma16816(acc[1][p*2+1], ah[1], rb + 2);
            }
            {   // f gate
                uint32_t rb[4];
                ldmx4(rb, cur + S_BF + bfoff + ks * 32);
                mma16816(accf[0][0], ah[0], rb + 0);
                mma16816(accf[0][1], ah[0], rb + 2);
                mma16816(accf[1][0], ah[1], rb + 0);
                mma16816(accf[1][1], ah[1], rb + 2);
            }
        }

        // ---- f epilogue at end of each d (every 2 chunks) ----
        if (kc & 1) {
            const int d = kc >> 1;
#pragma unroll
            for (int fm = 0; fm < 2; fm++)
#pragma unroll
                for (int rh = 0; rh < 2; rh++) {
                    int node = nb + wm * 32 + fm * 16 + (l >> 2) + rh * 8;
                    if (node < NN) {
#pragma unroll
                        for (int fn = 0; fn < 2; fn++) {
                            int col = fcol0 + wn * 16 + fn * 8 + (l & 3) * 2;
                            float2 fi  = *(const float2*)(f_in + (size_t)node * HH + col);
                            float2 nc2 = *(const float2*)(ncv + ((size_t)node * DEG + d) * HH + col);
                            float2 bf2 = *(const float2*)(bf + d * HH + col);
                            cag[fm][fn][rh*2+0] += sigm(accf[fm][fn][rh*2+0] + bf2.x + fi.x) * nc2.x;
                            cag[fm][fn][rh*2+1] += sigm(accf[fm][fn][rh*2+1] + bf2.y + fi.y) * nc2.y;
                        }
                    }
#pragma unroll
                    for (int fn = 0; fn < 2; fn++) {
                        accf[fm][fn][rh*2+0] = 0.f;
                        accf[fm][fn][rh*2+1] = 0.f;
                    }
                }
        }

        if (have_next) {
            CP_WAIT0();
            __syncthreads();
        }
    }

    // ---- final epilogue: cols [nhalf*64, nhalf*64+64), cag in regs ----
#pragma unroll
    for (int fm = 0; fm < 2; fm++)
#pragma unroll
        for (int rh = 0; rh < 2; rh++) {
            int node = nb + wm * 32 + fm * 16 + (l >> 2) + rh * 8;
            if (node >= NN) continue;
            const float* ib = iou_in + (size_t)node * NOUT;
#pragma unroll
            for (int g = 0; g < 2; g++) {
                int col = (nhalf * 8 + wn * 2 + g) * 8 + (l & 3) * 2;  // == fcol0 + wn*16 + g*8 + (l&3)*2
                float2 ii = *(const float2*)(ib + col);
                float2 oo = *(const float2*)(ib + HH + col);
                float2 uu = *(const float2*)(ib + 2 * HH + col);
                float2 bi = *(const float2*)(ba + col);
                float2 bo = *(const float2*)(ba + HH + col);
                float2 bu = *(const float2*)(ba + 2 * HH + col);
                float hv[2], cv[2];
#pragma unroll
                for (int e = 0; e < 2; e++) {
                    float iv = acc[fm][g*3+0][rh*2+e] + ((e) ? ii.y + bi.y : ii.x + bi.x);
                    float ov = acc[fm][g*3+1][rh*2+e] + ((e) ? oo.y + bo.y : oo.x + bo.x);
                    float uv = acc[fm][g*3+2][rh*2+e] + ((e) ? uu.y + bu.y : uu.x + bu.x);
                    float c  = sigm(iv) * tanhf(uv) + cag[fm][g][rh*2+e];
                    cv[e] = c;
                    hv[e] = sigm(ov) * tanhf(c);
                }
                *(float2*)(out + (size_t)node * HH + col) = make_float2(hv[0], hv[1]);
                *(float2*)(out + (size_t)NN * HH + (size_t)node * HH + col) = make_float2(cv[0], cv[1]);
            }
        }
#undef LOAD_CHUNK
}

// ---------------- launch ----------------
extern "C" void kernel_launch(void* const* d_in, const int* in_sizes, int n_in,
                              void* d_out, int out_size) {
    const float* nh     = (const float*)d_in[0];
    const float* ncv    = (const float*)d_in[1];
    const float* f_in   = (const float*)d_in[2];
    const float* iou_in = (const float*)d_in[3];
    const float* Uf     = (const float*)d_in[4];
    const float* bf     = (const float*)d_in[5];
    const float* Ua     = (const float*)d_in[6];
    const float* ba     = (const float*)d_in[7];
    float* out = (float*)d_out;

    prep_weights<<<2048, 256>>>(Uf, Ua);
    prep_a<<<(int)(((size_t)NPAD * (KTOT / 8) + 255) / 256), 256>>>(nh);

    cudaFuncSetAttribute(fused_cell, cudaFuncAttributeMaxDynamicSharedMemorySize, SMEM_TOTAL);
    dim3 grid((NN + 63) / 64, 2);
    fused_cell<<<grid, 256, SMEM_TOTAL>>>(ncv, f_in, iou_in, bf, ba, out);
}